// round 11
// baseline (speedup 1.0000x reference)
#include <cuda_runtime.h>
#include <cuda_fp16.h>
#include <cstdint>
#include <math.h>

#define BB 1024
#define DD 512
#define HH 1024
#define TT 8
#define EE 18

// ---------------------------------------------------------------------------
// Device scratch (no cudaMalloc allowed)
// ---------------------------------------------------------------------------
__device__ __half g_w1[2][EE * DD * HH];   // W1 transposed [e][n(H)][k(D)] fp16
__device__ __half g_w2[2][EE * HH * DD];   // W2 transposed [e][n(D)][k(H)] fp16
__device__ __half g_ah[BB * 9 * DD];       // activation plane (inputs / x1) fp16
__device__ __half g_hh[BB * EE * HH];      // hidden plane fp16
__device__ float g_eo  [BB * EE * DD];
__device__ float g_gate[BB * 9 * EE];
__device__ float g_x1  [BB * 9 * DD];

// ---------------------------------------------------------------------------
__device__ __forceinline__ uint32_t smem_u32(const void* p) {
    uint32_t a;
    asm("{ .reg .u64 t; cvta.to.shared.u64 t, %1; cvt.u32.u64 %0, t; }" : "=r"(a) : "l"(p));
    return a;
}
__device__ __forceinline__ void cp16(uint32_t dst, const void* src) {
    asm volatile("cp.async.cg.shared.global [%0], [%1], 16;" :: "r"(dst), "l"(src) : "memory");
}
#define CP_COMMIT() asm volatile("cp.async.commit_group;" ::: "memory")
#define CP_WAIT(n)  asm volatile("cp.async.wait_group %0;" :: "n"(n) : "memory")
#define LDSM4(r, addr) \
    asm volatile("ldmatrix.sync.aligned.m8n8.x4.shared.b16 {%0,%1,%2,%3}, [%4];" \
        : "=r"((r)[0]), "=r"((r)[1]), "=r"((r)[2]), "=r"((r)[3]) : "r"(addr))

__device__ __forceinline__ void mma16816(float* c, const uint32_t* a, const uint32_t* b) {
    asm volatile(
        "mma.sync.aligned.m16n8k16.row.col.f32.f16.f16.f32 "
        "{%0,%1,%2,%3}, {%4,%5,%6,%7}, {%8,%9}, {%0,%1,%2,%3};"
        : "+f"(c[0]), "+f"(c[1]), "+f"(c[2]), "+f"(c[3])
        : "r"(a[0]), "r"(a[1]), "r"(a[2]), "r"(a[3]), "r"(b[0]), "r"(b[1]));
}

// ===========================================================================
// Conversion kernels (run once per launch)
// ===========================================================================
__global__ __launch_bounds__(256) void conv_act(
    const float* __restrict__ src, __half* __restrict__ hi, int n4)
{
    int i = blockIdx.x * 256 + threadIdx.x;
    if (i >= n4) return;
    float4 v = ((const float4*)src)[i];
    __half h[4];
    h[0] = __float2half_rn(v.x); h[1] = __float2half_rn(v.y);
    h[2] = __float2half_rn(v.z); h[3] = __float2half_rn(v.w);
    ((uint2*)hi)[i] = *(uint2*)h;
}

// Transpose-round weights: W[e][k][n] fp32 -> Wt[e][n][k] fp16
// Vectorized: 1 float4 load + 1 uint2 store per thread, conflict-free smem.
__global__ __launch_bounds__(256) void conv_wt(
    const float* __restrict__ W, __half* __restrict__ Wt, int Kd, int Nd)
{
    __shared__ float t[32][33];
    const int e  = blockIdx.z;
    const int k0 = blockIdx.x * 32, n0 = blockIdx.y * 32;
    const int r = threadIdx.x >> 3;     // 0..31
    const int c = threadIdx.x & 7;      // 0..7
    const float* We = W + (size_t)e * Kd * Nd;

    float4 v = *(const float4*)(We + (size_t)(k0 + r) * Nd + n0 + c * 4);
    t[r][c * 4 + 0] = v.x; t[r][c * 4 + 1] = v.y;
    t[r][c * 4 + 2] = v.z; t[r][c * 4 + 3] = v.w;
    __syncthreads();

    __half h[4];
    h[0] = __float2half_rn(t[c * 4 + 0][r]);
    h[1] = __float2half_rn(t[c * 4 + 1][r]);
    h[2] = __float2half_rn(t[c * 4 + 2][r]);
    h[3] = __float2half_rn(t[c * 4 + 3][r]);
    *(uint2*)(Wt + ((size_t)e * Nd + n0 + r) * Kd + k0 + c * 4) = *(uint2*)h;
}

// ===========================================================================
// Tensor-core expert GEMM, single-product fp16:
//   C[b,e,n] = act( sum_k A(b,e)[k] * Bt[e][n][k] + bias[e,n] )
// Tile 128x128, BK=32, 4-stage cp.async pipeline, XOR-swizzled 64B rows.
// SMEM stage 16KB: [A][B] planes of 128 x 64B (32 fp16).
// ===========================================================================
template<bool GATHER, bool OUT1, int NMAT, int K>
__global__ __launch_bounds__(256, 2) void tc_gemm(
    const __half* __restrict__ Ahp, int aStride,
    const __half* __restrict__ Bt,
    const float* __restrict__ bias,
    float* __restrict__ Cf, __half* __restrict__ Chp)
{
    constexpr int NS = K / 32;
    constexpr uint32_t PLANE = 8192;    // 128 rows * 64B
    constexpr uint32_t STAGE = 16384;   // 2 planes

    extern __shared__ char smraw[];
    const uint32_t smbase = smem_u32(smraw);

    const int e    = blockIdx.z;
    const int m0   = blockIdx.y * 128;
    const int n0   = blockIdx.x * 128;
    const int tid  = threadIdx.x;
    const int wid  = tid >> 5;
    const int lane = tid & 31;
    const int g    = lane >> 2;
    const int q    = lane & 3;
    const int mbase = (wid >> 2) * 64;
    const int nbase = (wid & 3) * 32;
    const int xr   = lane & 3;

    const __half* A_b  = Ahp + (size_t)m0 * aStride + (size_t)(GATHER ? (e >> 1) : e) * K;
    const __half* Bt_b = Bt + ((size_t)e * NMAT + n0) * K;

    uint32_t arow[4], brow[2];
    #pragma unroll
    for (int i = 0; i < 4; i++)
        arow[i] = (uint32_t)(mbase + i * 16 + (lane & 15)) * 64u;
    #pragma unroll
    for (int jj = 0; jj < 2; jj++)
        brow[jj] = (uint32_t)(nbase + jj * 16 + (lane & 7) + (((lane >> 4) & 1) << 3)) * 64u;
    const int akc0 = lane >> 4;
    const int bkc0 = (lane >> 3) & 1;

    float acc[4][4][4];
    #pragma unroll
    for (int i = 0; i < 4; i++)
        #pragma unroll
        for (int j = 0; j < 4; j++)
            #pragma unroll
            for (int c = 0; c < 4; c++) acc[i][j][c] = 0.f;

    const int lr = tid >> 2, lc = tid & 3;

    auto loadStage = [&](int s, int buf) {
        const int k0 = s * 32;
        const uint32_t sb = smbase + (uint32_t)buf * STAGE;
        #pragma unroll
        for (int half = 0; half < 2; half++) {
            const int r = half * 64 + lr;
            const uint32_t ro = (uint32_t)r * 64u + (uint32_t)((lc ^ (r & 3)) << 4);
            cp16(sb + ro,         A_b  + (size_t)r * aStride + k0 + lc * 8);
            cp16(sb + PLANE + ro, Bt_b + (size_t)r * K + k0 + lc * 8);
        }
        CP_COMMIT();
    };

    auto compute = [&](int buf) {
        const uint32_t sb = smbase + (uint32_t)buf * STAGE;
        #pragma unroll
        for (int ks = 0; ks < 2; ks++) {
            const uint32_t ao = (uint32_t)(((akc0 + 2 * ks) ^ xr) << 4);
            const uint32_t bo = (uint32_t)(((bkc0 + 2 * ks) ^ xr) << 4);
            uint32_t af[4][4], bf[2][4];
            LDSM4(bf[0], sb + PLANE + brow[0] + bo);
            LDSM4(bf[1], sb + PLANE + brow[1] + bo);
            #pragma unroll
            for (int i = 0; i < 4; i++)
                LDSM4(af[i], sb + arow[i] + ao);
            #pragma unroll
            for (int i = 0; i < 4; i++)
                #pragma unroll
                for (int j = 0; j < 4; j++)
                    mma16816(acc[i][j], af[i], &bf[j >> 1][(j & 1) * 2]);
        }
    };

    // ---- 4-stage pipeline, one barrier per slab, exact tail waits ----
    loadStage(0, 0);
    loadStage(1, 1);
    loadStage(2, 2);
    int buf = 0;
    for (int s = 0; s < NS; s++) {
        if (s < NS - 2)      { CP_WAIT(2); }
        else if (s == NS - 2){ CP_WAIT(1); }
        else                 { CP_WAIT(0); }
        __syncthreads();
        if (s + 3 < NS) loadStage(s + 3, (buf + 3) & 3);
        compute(buf);
        buf = (buf + 1) & 3;
    }

    // ---- epilogue ----
    #pragma unroll
    for (int i = 0; i < 4; i++) {
        const int rr0 = m0 + mbase + i * 16 + g;
        #pragma unroll
        for (int j = 0; j < 4; j++) {
            const int col = nbase + j * 8 + 2 * q;
            const float2 bb = *(const float2*)(bias + (size_t)e * NMAT + n0 + col);
            float v0 = acc[i][j][0] + bb.x;
            float v1 = acc[i][j][1] + bb.y;
            float v2 = acc[i][j][2] + bb.x;
            float v3 = acc[i][j][3] + bb.y;
            const size_t off0 = ((size_t)rr0 * EE + e) * NMAT + n0 + col;
            const size_t off1 = ((size_t)(rr0 + 8) * EE + e) * NMAT + n0 + col;
            if (OUT1) {
                v0 = fmaxf(v0, 0.f); v1 = fmaxf(v1, 0.f);
                v2 = fmaxf(v2, 0.f); v3 = fmaxf(v3, 0.f);
                __half h[4];
                h[0] = __float2half_rn(v0); h[1] = __float2half_rn(v1);
                h[2] = __float2half_rn(v2); h[3] = __float2half_rn(v3);
                *(uint32_t*)(Chp + off0) = *(uint32_t*)&h[0];
                *(uint32_t*)(Chp + off1) = *(uint32_t*)&h[2];
            } else {
                *(float2*)(Cf + off0) = make_float2(v0, v1);
                *(float2*)(Cf + off1) = make_float2(v2, v3);
            }
        }
    }
}

// ---------------------------------------------------------------------------
// Gating: g[b,m,:] = softmax( x[b,m,:] @ Wg[m] + bg[m] ) + add(m)
// ---------------------------------------------------------------------------
template<int M>
__global__ __launch_bounds__(256) void gate_kernel(
    const float* __restrict__ x, int xRows,
    const float* __restrict__ Wg, const float* __restrict__ bg,
    const float* __restrict__ sew_task, const float* __restrict__ sew_shared,
    int layer, float* __restrict__ g)
{
    __shared__ float sWg[DD * EE];
    __shared__ float sLog[32][EE];
    const int m  = blockIdx.y;
    const int b0 = blockIdx.x * 32;

    const float* Wgm = Wg + (size_t)m * DD * EE;
    for (int i = threadIdx.x; i < DD * EE; i += 256) sWg[i] = Wgm[i];
    __syncthreads();

    for (int p = threadIdx.x; p < 32 * EE; p += 256) {
        const int bl = p / EE, e = p % EE;
        const float* xr = x + ((size_t)(b0 + bl) * xRows + m) * DD;
        float s = bg[m * EE + e];
        for (int d = 0; d < DD; d += 4) {
            float4 xv = *(const float4*)(xr + d);
            s = fmaf(xv.x, sWg[(d + 0) * EE + e], s);
            s = fmaf(xv.y, sWg[(d + 1) * EE + e], s);
            s = fmaf(xv.z, sWg[(d + 2) * EE + e], s);
            s = fmaf(xv.w, sWg[(d + 3) * EE + e], s);
        }
        sLog[bl][e] = s;
    }
    __syncthreads();

    if (threadIdx.x < 32) {
        const int bl = threadIdx.x;
        float mx = -1e30f;
        #pragma unroll
        for (int e = 0; e < EE; e++) mx = fmaxf(mx, sLog[bl][e]);
        float ex[EE]; float sum = 0.f;
        #pragma unroll
        for (int e = 0; e < EE; e++) { ex[e] = expf(sLog[bl][e] - mx); sum += ex[e]; }
        const float inv = 1.f / sum;
        float* gp = g + ((size_t)(b0 + bl) * M + m) * EE;
        #pragma unroll
        for (int e = 0; e < EE; e++) gp[e] = ex[e] * inv;
        if (m < TT) {
            gp[2 * m + 0] += sew_task[(m * 2 + layer) * 2 + 0];
            gp[2 * m + 1] += sew_task[(m * 2 + layer) * 2 + 1];
        } else {
            gp[16] += sew_shared[0];
            gp[17] += sew_shared[1];
        }
    }
}

// ---------------------------------------------------------------------------
// Combine: out[b,m,d] = sum_e g[b,m,e] * eo[b,e,d]; optionally also write
// the fp16 plane of the result (feeds next layer's GEMM1).
// ---------------------------------------------------------------------------
template<int M, bool PLANES>
__global__ __launch_bounds__(512) void combine_kernel(
    const float* __restrict__ g, const float* __restrict__ eo,
    float* __restrict__ out, __half* __restrict__ ohp)
{
    __shared__ float sg[M * EE];
    const int b = blockIdx.x;
    for (int i = threadIdx.x; i < M * EE; i += 512) sg[i] = g[(size_t)b * M * EE + i];
    __syncthreads();

    const int d = threadIdx.x;
    float acc[M];
    #pragma unroll
    for (int mm = 0; mm < M; mm++) acc[mm] = 0.f;

    const float* eob = eo + (size_t)b * EE * DD + d;
    #pragma unroll
    for (int e = 0; e < EE; e++) {
        const float v = eob[(size_t)e * DD];
        #pragma unroll
        for (int mm = 0; mm < M; mm++) acc[mm] = fmaf(sg[mm * EE + e], v, acc[mm]);
    }
    #pragma unroll
    for (int mm = 0; mm < M; mm++) {
        const size_t off = ((size_t)b * M + mm) * DD + d;
        out[off] = acc[mm];
        if (PLANES) ohp[off] = __float2half_rn(acc[mm]);
    }
}

// ---------------------------------------------------------------------------
extern "C" void kernel_launch(void* const* d_in, const int* in_sizes, int n_in,
                              void* d_out, int out_size)
{
    const float* inputs   = (const float*)d_in[0];
    const float* W1_0     = (const float*)d_in[1];
    const float* b1_0     = (const float*)d_in[2];
    const float* W2_0     = (const float*)d_in[3];
    const float* b2_0     = (const float*)d_in[4];
    const float* Wg_0     = (const float*)d_in[5];
    const float* bg_0     = (const float*)d_in[6];
    const float* W1_1     = (const float*)d_in[7];
    const float* b1_1     = (const float*)d_in[8];
    const float* W2_1     = (const float*)d_in[9];
    const float* b2_1     = (const float*)d_in[10];
    const float* Wg_1     = (const float*)d_in[11];
    const float* bg_1     = (const float*)d_in[12];
    const float* sew_task = (const float*)d_in[13];
    const float* sew_shared = (const float*)d_in[14];

    __half *w1_0p, *w1_1p, *w2_0p, *w2_1p, *ah, *hh;
    float *p_eo, *p_gate, *p_x1;
    cudaGetSymbolAddress((void**)&w1_0p, g_w1);
    cudaGetSymbolAddress((void**)&w2_0p, g_w2);
    w1_1p = w1_0p + (size_t)EE * DD * HH;
    w2_1p = w2_0p + (size_t)EE * HH * DD;
    cudaGetSymbolAddress((void**)&ah, g_ah);
    cudaGetSymbolAddress((void**)&hh, g_hh);
    cudaGetSymbolAddress((void**)&p_eo,   g_eo);
    cudaGetSymbolAddress((void**)&p_gate, g_gate);
    cudaGetSymbolAddress((void**)&p_x1,   g_x1);

    const int SMEM_DYN = 4 * 16384;   // 64 KB (4 stages x 2 planes)
    cudaFuncSetAttribute(tc_gemm<true,  true,  HH, DD>,
                         cudaFuncAttributeMaxDynamicSharedMemorySize, SMEM_DYN);
    cudaFuncSetAttribute(tc_gemm<false, false, DD, HH>,
                         cudaFuncAttributeMaxDynamicSharedMemorySize, SMEM_DYN);

    // ---- conversions (once per launch) ----
    conv_wt<<<dim3(DD/32, HH/32, EE), 256>>>(W1_0, w1_0p, DD, HH);
    conv_wt<<<dim3(DD/32, HH/32, EE), 256>>>(W1_1, w1_1p, DD, HH);
    conv_wt<<<dim3(HH/32, DD/32, EE), 256>>>(W2_0, w2_0p, HH, DD);
    conv_wt<<<dim3(HH/32, DD/32, EE), 256>>>(W2_1, w2_1p, HH, DD);
    {
        const int n4 = BB * 9 * DD / 4;
        conv_act<<<(n4 + 255) / 256, 256>>>(inputs, ah, n4);
    }

    const dim3 blk(256);

    // ---- Layer 0 ----
    tc_gemm<true,  true,  HH, DD><<<dim3(HH/128, BB/128, EE), blk, SMEM_DYN>>>(
        ah, 9 * DD, w1_0p, b1_0, nullptr, hh);
    tc_gemm<false, false, DD, HH><<<dim3(DD/128, BB/128, EE), blk, SMEM_DYN>>>(
        hh, EE * HH, w2_0p, b2_0, p_eo, nullptr);
    gate_kernel<9><<<dim3(BB/32, 9), blk>>>(inputs, 9, Wg_0, bg_0, sew_task, sew_shared, 0, p_gate);
    combine_kernel<9, true><<<BB, 512>>>(p_gate, p_eo, p_x1, ah);

    // ---- Layer 1 ----
    tc_gemm<true,  true,  HH, DD><<<dim3(HH/128, BB/128, EE), blk, SMEM_DYN>>>(
        ah, 9 * DD, w1_1p, b1_1, nullptr, hh);
    tc_gemm<false, false, DD, HH><<<dim3(DD/128, BB/128, EE), blk, SMEM_DYN>>>(
        hh, EE * HH, w2_1p, b2_1, p_eo, nullptr);
    gate_kernel<8><<<dim3(BB/32, 8), blk>>>(p_x1, 9, Wg_1, bg_1, sew_task, sew_shared, 1, p_gate);
    combine_kernel<8, false><<<BB, 512>>>(p_gate, p_eo, (float*)d_out, nullptr);
}

// round 14
// speedup vs baseline: 1.1055x; 1.1055x over previous
#include <cuda_runtime.h>
#include <cuda_fp16.h>
#include <cstdint>
#include <math.h>

#define BB 1024
#define DD 512
#define HH 1024
#define TT 8
#define EE 18

// ---------------------------------------------------------------------------
// Device scratch (no cudaMalloc allowed). All packed operand arrays use the
// tiled layout: [...][tile][slab] -> 4096 halfs = 128 rows x 32 k (64B rows,
// 16B chunks XOR-swizzled by (row&3)).
// ---------------------------------------------------------------------------
__device__ __align__(128) __half g_w1[2][EE * DD * HH];  // [e][ntile(8)][slab(16)][4096]
__device__ __align__(128) __half g_w2[2][EE * HH * DD];  // [e][ntile(4)][slab(32)][4096]
__device__ __align__(128) __half g_apk[BB * 9 * DD];     // [task(9)][btile(8)][slab(16)][4096]
__device__ __align__(128) __half g_hpk[BB * EE * HH];    // [e(18)][btile(8)][slab(32)][4096]
__device__ float g_eo  [BB * EE * DD];
__device__ float g_gate[BB * 9 * EE];
__device__ float g_x1  [BB * 9 * DD];

// ---------------------------------------------------------------------------
__device__ __forceinline__ uint32_t smem_u32(const void* p) {
    uint32_t a;
    asm("{ .reg .u64 t; cvta.to.shared.u64 t, %1; cvt.u32.u64 %0, t; }" : "=r"(a) : "l"(p));
    return a;
}
#define MBARRIER_INIT(addr, cnt) \
    asm volatile("mbarrier.init.shared.b64 [%0], %1;" :: "r"((uint32_t)(addr)), "r"((uint32_t)(cnt)) : "memory")
#define MBARRIER_EXPECT_TX(addr, bytes) \
    asm volatile("mbarrier.arrive.expect_tx.shared.b64 _, [%0], %1;" :: "r"((uint32_t)(addr)), "r"((uint32_t)(bytes)) : "memory")
#define BULK_LOAD(dst, src, bytes, mbar) \
    asm volatile("cp.async.bulk.shared::cluster.global.mbarrier::complete_tx::bytes [%0], [%1], %2, [%3];" \
        :: "r"((uint32_t)(dst)), "l"(src), "r"((uint32_t)(bytes)), "r"((uint32_t)(mbar)) : "memory")
#define MBARRIER_WAIT_PARITY(mbar_smem_addr, phase_parity) do { \
    uint32_t _mbar = (uint32_t)(mbar_smem_addr); \
    uint32_t _parity = (uint32_t)(phase_parity); \
    uint32_t _done; \
    asm volatile("{\n\t.reg .pred p;\n\tmbarrier.try_wait.parity.acquire.cta.shared::cta.b64 p, [%1], %2;\n\tselp.b32 %0, 1, 0, p;\n\t}" \
        : "=r"(_done) : "r"(_mbar), "r"(_parity) : "memory"); \
    if (!_done) { \
        asm volatile("{\n\t.reg .pred P1;\n\tWAIT_LOOP_%=:\n\tmbarrier.try_wait.parity.acquire.cta.shared::cta.b64 P1, [%0], %1, 0x989680;\n\t@P1 bra.uni WAIT_DONE_%=;\n\tbra.uni WAIT_LOOP_%=;\n\tWAIT_DONE_%=:\n\t}" \
            :: "r"(_mbar), "r"(_parity) : "memory"); \
    } \
} while(0)

#define LDSM4(r, addr) \
    asm volatile("ldmatrix.sync.aligned.m8n8.x4.shared.b16 {%0,%1,%2,%3}, [%4];" \
        : "=r"((r)[0]), "=r"((r)[1]), "=r"((r)[2]), "=r"((r)[3]) : "r"(addr))

__device__ __forceinline__ void mma16816(float* c, const uint32_t* a, const uint32_t* b) {
    asm volatile(
        "mma.sync.aligned.m16n8k16.row.col.f32.f16.f16.f32 "
        "{%0,%1,%2,%3}, {%4,%5,%6,%7}, {%8,%9}, {%0,%1,%2,%3};"
        : "+f"(c[0]), "+f"(c[1]), "+f"(c[2]), "+f"(c[3])
        : "r"(a[0]), "r"(a[1]), "r"(a[2]), "r"(a[3]), "r"(b[0]), "r"(b[1]));
}

// Packed offset for element (row 0..127, kk 0..31) within one 4096-half slab.
__device__ __forceinline__ int pk_off(int row, int kk) {
    const int chunk = kk >> 3;
    return row * 32 + (((chunk) ^ (row & 3)) << 3) + (kk & 7);
}

// ===========================================================================
// Conversion kernels (run once per launch)
// ===========================================================================
// inputs (B,9,D) fp32 -> apk [m][b>>7][d>>5][pk(row=b&127, kk=d&31)]
__global__ __launch_bounds__(128) void conv_act(
    const float* __restrict__ src, __half* __restrict__ apk)
{
    const int b = blockIdx.x, m = blockIdx.y, d = threadIdx.x * 4;
    float4 v = *(const float4*)(src + ((size_t)b * 9 + m) * DD + d);
    __half h[4];
    h[0] = __float2half_rn(v.x); h[1] = __float2half_rn(v.y);
    h[2] = __float2half_rn(v.z); h[3] = __float2half_rn(v.w);
    const size_t off = (((size_t)m * 8 + (b >> 7)) * (DD / 32) + (d >> 5)) * 4096
                     + pk_off(b & 127, d & 31);
    *(uint2*)(apk + off) = *(uint2*)h;
}

// W[e][k][n] fp32 -> Wpk [e][n>>7][k>>5][pk(row=n&127, kk=k&31)]
__global__ __launch_bounds__(256) void conv_wt(
    const float* __restrict__ W, __half* __restrict__ Wpk, int Kd, int Nd)
{
    __shared__ float t[32][33];
    const int e  = blockIdx.z;
    const int k0 = blockIdx.x * 32, n0 = blockIdx.y * 32;
    const int r = threadIdx.x >> 3;     // 0..31
    const int c = threadIdx.x & 7;      // 0..7
    const float* We = W + (size_t)e * Kd * Nd;

    float4 v = *(const float4*)(We + (size_t)(k0 + r) * Nd + n0 + c * 4);
    t[r][c * 4 + 0] = v.x; t[r][c * 4 + 1] = v.y;
    t[r][c * 4 + 2] = v.z; t[r][c * 4 + 3] = v.w;
    __syncthreads();

    __half h[4];
    h[0] = __float2half_rn(t[c * 4 + 0][r]);
    h[1] = __float2half_rn(t[c * 4 + 1][r]);
    h[2] = __float2half_rn(t[c * 4 + 2][r]);
    h[3] = __float2half_rn(t[c * 4 + 3][r]);
    const int n = n0 + r;
    const size_t off = (((size_t)e * (Nd / 128) + (n >> 7)) * (Kd / 32) + (k0 >> 5)) * 4096
                     + pk_off(n & 127, c * 4);
    *(uint2*)(Wpk + off) = *(uint2*)h;
}

// ===========================================================================
// Tensor-core expert GEMM, single-product fp16, packed bulk-copy operands:
//   C[b,e,n] = act( sum_k A(b,e)[k] * Bt[e][n][k] + bias[e,n] )
// Tile 128x128, BK=32, 4-stage pipeline: per slab 2x cp.async.bulk (8KB each)
// into [A][B] smem planes + mbarrier; ldmatrix fragments; mma.
// OUT1: relu + write packed h-plane; else fp32 row-major write.
// ===========================================================================
template<bool GATHER, bool OUT1, int NMAT, int K>
__global__ __launch_bounds__(256, 2) void tc_gemm(
    const __half* __restrict__ Apk,
    const __half* __restrict__ Bpk,
    const float* __restrict__ bias,
    float* __restrict__ Cf, __half* __restrict__ Chp)
{
    constexpr int NS = K / 32;
    constexpr uint32_t PLANE = 8192;
    constexpr uint32_t STAGE = 16384;

    extern __shared__ char smraw[];
    __shared__ __align__(8) unsigned long long s_mb[4];
    const uint32_t smbase = smem_u32(smraw);
    const uint32_t mbbase = smem_u32(&s_mb[0]);

    const int e    = blockIdx.z;
    const int n0   = blockIdx.x * 128;
    const int tid  = threadIdx.x;
    const int wid  = tid >> 5;
    const int lane = tid & 31;
    const int g    = lane >> 2;
    const int q    = lane & 3;
    const int mbase = (wid >> 2) * 64;
    const int nbase = (wid & 3) * 32;
    const int xr   = lane & 3;

    const __half* A_b = Apk + ((size_t)(GATHER ? (e >> 1) : e) * 8 + blockIdx.y) * (size_t)NS * 4096;
    const __half* B_b = Bpk + ((size_t)e * (NMAT / 128) + blockIdx.x) * (size_t)NS * 4096;

    uint32_t arow[4], brow[2];
    #pragma unroll
    for (int i = 0; i < 4; i++)
        arow[i] = (uint32_t)(mbase + i * 16 + (lane & 15)) * 64u;
    #pragma unroll
    for (int jj = 0; jj < 2; jj++)
        brow[jj] = (uint32_t)(nbase + jj * 16 + (lane & 7) + (((lane >> 4) & 1) << 3)) * 64u;
    const int akc0 = lane >> 4;
    const int bkc0 = (lane >> 3) & 1;

    float acc[4][4][4];
    #pragma unroll
    for (int i = 0; i < 4; i++)
        #pragma unroll
        for (int j = 0; j < 4; j++)
            #pragma unroll
            for (int c = 0; c < 4; c++) acc[i][j][c] = 0.f;

    if (tid == 0) {
        #pragma unroll
        for (int s = 0; s < 4; s++) MBARRIER_INIT(mbbase + s * 8, 1);
    }
    __syncthreads();

    auto issueSlab = [&](int s) {
        const int slot = s & 3;
        const uint32_t sb = smbase + (uint32_t)slot * STAGE;
        const uint32_t mb = mbbase + slot * 8;
        MBARRIER_EXPECT_TX(mb, 16384u);
        BULK_LOAD(sb,         A_b + (size_t)s * 4096, 8192u, mb);
        BULK_LOAD(sb + PLANE, B_b + (size_t)s * 4096, 8192u, mb);
    };

    auto compute = [&](int slot) {
        const uint32_t sb = smbase + (uint32_t)slot * STAGE;
        #pragma unroll
        for (int ks = 0; ks < 2; ks++) {
            const uint32_t ao = (uint32_t)(((akc0 + 2 * ks) ^ xr) << 4);
            const uint32_t bo = (uint32_t)(((bkc0 + 2 * ks) ^ xr) << 4);
            uint32_t af[4][4], bf[2][4];
            LDSM4(bf[0], sb + PLANE + brow[0] + bo);
            LDSM4(bf[1], sb + PLANE + brow[1] + bo);
            #pragma unroll
            for (int i = 0; i < 4; i++)
                LDSM4(af[i], sb + arow[i] + ao);
            #pragma unroll
            for (int i = 0; i < 4; i++)
                #pragma unroll
                for (int j = 0; j < 4; j++)
                    mma16816(acc[i][j], af[i], &bf[j >> 1][(j & 1) * 2]);
        }
    };

    if (tid == 0) { issueSlab(0); issueSlab(1); issueSlab(2); }

    for (int s = 0; s < NS; s++) {
        MBARRIER_WAIT_PARITY(mbbase + (s & 3) * 8, (s >> 2) & 1);
        compute(s & 3);
        __syncthreads();
        if (tid == 0 && s + 3 < NS) issueSlab(s + 3);
    }

    // ---- epilogue ----
    if (OUT1) {
        // packed h layout: [e][btile][hslab][pk(row, kk)]
        // This warp's 32 columns live entirely in slab (n0+nbase)>>5.
        const size_t base = (((size_t)e * 8 + blockIdx.y) * (NMAT / 32)
                            + (size_t)((n0 + nbase) >> 5)) * 4096;
        #pragma unroll
        for (int i = 0; i < 4; i++) {
            const int row = mbase + i * 16 + g;      // (row+8)&3 == row&3
            const int sw = (row & 3);
            #pragma unroll
            for (int j = 0; j < 4; j++) {
                const int col = nbase + j * 8 + 2 * q;
                const float2 bb = *(const float2*)(bias + (size_t)e * NMAT + n0 + col);
                float v0 = fmaxf(acc[i][j][0] + bb.x, 0.f);
                float v1 = fmaxf(acc[i][j][1] + bb.y, 0.f);
                float v2 = fmaxf(acc[i][j][2] + bb.x, 0.f);
                float v3 = fmaxf(acc[i][j][3] + bb.y, 0.f);
                __half h[4];
                h[0] = __float2half_rn(v0); h[1] = __float2half_rn(v1);
                h[2] = __float2half_rn(v2); h[3] = __float2half_rn(v3);
                const int inner = ((j ^ sw) << 3) + 2 * q;   // kk = j*8 + 2q within slab
                *(uint32_t*)(Chp + base + (size_t)row * 32 + inner)       = *(uint32_t*)&h[0];
                *(uint32_t*)(Chp + base + (size_t)(row + 8) * 32 + inner) = *(uint32_t*)&h[2];
            }
        }
    } else {
        const int m0 = blockIdx.y * 128;
        #pragma unroll
        for (int i = 0; i < 4; i++) {
            const int rr0 = m0 + mbase + i * 16 + g;
            #pragma unroll
            for (int j = 0; j < 4; j++) {
                const int col = nbase + j * 8 + 2 * q;
                const float2 bb = *(const float2*)(bias + (size_t)e * NMAT + n0 + col);
                const size_t off0 = ((size_t)rr0 * EE + e) * NMAT + n0 + col;
                const size_t off1 = ((size_t)(rr0 + 8) * EE + e) * NMAT + n0 + col;
                *(float2*)(Cf + off0) = make_float2(acc[i][j][0] + bb.x, acc[i][j][1] + bb.y);
                *(float2*)(Cf + off1) = make_float2(acc[i][j][2] + bb.x, acc[i][j][3] + bb.y);
            }
        }
    }
}

// ---------------------------------------------------------------------------
// Gating: g[b,m,:] = softmax( x[b,m,:] @ Wg[m] + bg[m] ) + add(m)
// ---------------------------------------------------------------------------
template<int M>
__global__ __launch_bounds__(256) void gate_kernel(
    const float* __restrict__ x, int xRows,
    const float* __restrict__ Wg, const float* __restrict__ bg,
    const float* __restrict__ sew_task, const float* __restrict__ sew_shared,
    int layer, float* __restrict__ g)
{
    __shared__ float sWg[DD * EE];
    __shared__ float sLog[32][EE];
    const int m  = blockIdx.y;
    const int b0 = blockIdx.x * 32;

    const float* Wgm = Wg + (size_t)m * DD * EE;
    for (int i = threadIdx.x; i < DD * EE; i += 256) sWg[i] = Wgm[i];
    __syncthreads();

    for (int p = threadIdx.x; p < 32 * EE; p += 256) {
        const int bl = p / EE, e = p % EE;
        const float* xr = x + ((size_t)(b0 + bl) * xRows + m) * DD;
        float s = bg[m * EE + e];
        for (int d = 0; d < DD; d += 4) {
            float4 xv = *(const float4*)(xr + d);
            s = fmaf(xv.x, sWg[(d + 0) * EE + e], s);
            s = fmaf(xv.y, sWg[(d + 1) * EE + e], s);
            s = fmaf(xv.z, sWg[(d + 2) * EE + e], s);
            s = fmaf(xv.w, sWg[(d + 3) * EE + e], s);
        }
        sLog[bl][e] = s;
    }
    __syncthreads();

    if (threadIdx.x < 32) {
        const int bl = threadIdx.x;
        float mx = -1e30f;
        #pragma unroll
        for (int e = 0; e < EE; e++) mx = fmaxf(mx, sLog[bl][e]);
        float ex[EE]; float sum = 0.f;
        #pragma unroll
        for (int e = 0; e < EE; e++) { ex[e] = expf(sLog[bl][e] - mx); sum += ex[e]; }
        const float inv = 1.f / sum;
        float* gp = g + ((size_t)(b0 + bl) * M + m) * EE;
        #pragma unroll
        for (int e = 0; e < EE; e++) gp[e] = ex[e] * inv;
        if (m < TT) {
            gp[2 * m + 0] += sew_task[(m * 2 + layer) * 2 + 0];
            gp[2 * m + 1] += sew_task[(m * 2 + layer) * 2 + 1];
        } else {
            gp[16] += sew_shared[0];
            gp[17] += sew_shared[1];
        }
    }
}

// ---------------------------------------------------------------------------
// Combine: out[b,m,d] = sum_e g[b,m,e] * eo[b,e,d]; optionally also write
// the packed fp16 activation plane (feeds next layer's GEMM1).
// ---------------------------------------------------------------------------
template<int M, bool PLANES>
__global__ __launch_bounds__(512) void combine_kernel(
    const float* __restrict__ g, const float* __restrict__ eo,
    float* __restrict__ out, __half* __restrict__ apk)
{
    __shared__ float sg[M * EE];
    const int b = blockIdx.x;
    for (int i = threadIdx.x; i < M * EE; i += 512) sg[i] = g[(size_t)b * M * EE + i];
    __syncthreads();

    const int d = threadIdx.x;
    float acc[M];
    #pragma unroll
    for (int mm = 0; mm < M; mm++) acc[mm] = 0.f;

    const float* eob = eo + (size_t)b * EE * DD + d;
    #pragma unroll
    for (int e = 0; e < EE; e++) {
        const float v = eob[(size_t)e * DD];
        #pragma unroll
        for (int mm = 0; mm < M; mm++) acc[mm] = fmaf(sg[mm * EE + e], v, acc[mm]);
    }
    #pragma unroll
    for (int mm = 0; mm < M; mm++) {
        out[((size_t)b * M + mm) * DD + d] = acc[mm];
        if (PLANES) {
            const size_t off = (((size_t)mm * 8 + (b >> 7)) * (DD / 32) + (d >> 5)) * 4096
                             + pk_off(b & 127, d & 31);
            apk[off] = __float2half_rn(acc[mm]);
        }
    }
}

// ---------------------------------------------------------------------------
extern "C" void kernel_launch(void* const* d_in, const int* in_sizes, int n_in,
                              void* d_out, int out_size)
{
    const float* inputs   = (const float*)d_in[0];
    const float* W1_0     = (const float*)d_in[1];
    const float* b1_0     = (const float*)d_in[2];
    const float* W2_0     = (const float*)d_in[3];
    const float* b2_0     = (const float*)d_in[4];
    const float* Wg_0     = (const float*)d_in[5];
    const float* bg_0     = (const float*)d_in[6];
    const float* W1_1     = (const float*)d_in[7];
    const float* b1_1     = (const float*)d_in[8];
    const float* W2_1     = (const float*)d_in[9];
    const float* b2_1     = (const float*)d_in[10];
    const float* Wg_1     = (const float*)d_in[11];
    const float* bg_1     = (const float*)d_in[12];
    const float* sew_task = (const float*)d_in[13];
    const float* sew_shared = (const float*)d_in[14];

    __half *w1_0p, *w1_1p, *w2_0p, *w2_1p, *apk, *hpk;
    float *p_eo, *p_gate, *p_x1;
    cudaGetSymbolAddress((void**)&w1_0p, g_w1);
    cudaGetSymbolAddress((void**)&w2_0p, g_w2);
    w1_1p = w1_0p + (size_t)EE * DD * HH;
    w2_1p = w2_0p + (size_t)EE * HH * DD;
    cudaGetSymbolAddress((void**)&apk, g_apk);
    cudaGetSymbolAddress((void**)&hpk, g_hpk);
    cudaGetSymbolAddress((void**)&p_eo,   g_eo);
    cudaGetSymbolAddress((void**)&p_gate, g_gate);
    cudaGetSymbolAddress((void**)&p_x1,   g_x1);

    const int SMEM_DYN = 4 * 16384;   // 64 KB (4 stages x 2 planes)
    cudaFuncSetAttribute(tc_gemm<true,  true,  HH, DD>,
                         cudaFuncAttributeMaxDynamicSharedMemorySize, SMEM_DYN);
    cudaFuncSetAttribute(tc_gemm<false, false, DD, HH>,
                         cudaFuncAttributeMaxDynamicSharedMemorySize, SMEM_DYN);

    // ---- conversions (once per launch) ----
    conv_wt<<<dim3(DD/32, HH/32, EE), 256>>>(W1_0, w1_0p, DD, HH);
    conv_wt<<<dim3(DD/32, HH/32, EE), 256>>>(W1_1, w1_1p, DD, HH);
    conv_wt<<<dim3(HH/32, DD/32, EE), 256>>>(W2_0, w2_0p, HH, DD);
    conv_wt<<<dim3(HH/32, DD/32, EE), 256>>>(W2_1, w2_1p, HH, DD);
    conv_act<<<dim3(BB, 9), 128>>>(inputs, apk);

    const dim3 blk(256);

    // ---- Layer 0 ----
    tc_gemm<true,  true,  HH, DD><<<dim3(HH/128, BB/128, EE), blk, SMEM_DYN>>>(
        apk, w1_0p, b1_0, nullptr, hpk);
    tc_gemm<false, false, DD, HH><<<dim3(DD/128, BB/128, EE), blk, SMEM_DYN>>>(
        hpk, w2_0p, b2_0, p_eo, nullptr);
    gate_kernel<9><<<dim3(BB/32, 9), blk>>>(inputs, 9, Wg_0, bg_0, sew_task, sew_shared, 0, p_gate);
    combine_kernel<9, true><<<BB, 512>>>(p_gate, p_eo, p_x1, apk);

    // ---- Layer 1 ----
    tc_gemm<true,  true,  HH, DD><<<dim3(HH/128, BB/128, EE), blk, SMEM_DYN>>>(
        apk, w1_1p, b1_1, nullptr, hpk);
    tc_gemm<false, false, DD, HH><<<dim3(DD/128, BB/128, EE), blk, SMEM_DYN>>>(
        hpk, w2_1p, b2_1, p_eo, nullptr);
    gate_kernel<8><<<dim3(BB/32, 8), blk>>>(p_x1, 9, Wg_1, bg_1, sew_task, sew_shared, 1, p_gate);
    combine_kernel<8, false><<<BB, 512>>>(p_gate, p_eo, (float*)d_out, nullptr);
}

// round 15
// speedup vs baseline: 1.6101x; 1.4565x over previous
#include <cuda_runtime.h>
#include <cuda_fp16.h>
#include <cstdint>
#include <math.h>

#define BB 1024
#define DD 512
#define HH 1024
#define TT 8
#define EE 18

// ---------------------------------------------------------------------------
// Device scratch (no cudaMalloc allowed). All packed operand arrays use the
// tiled layout: [...][tile][slab] -> 4096 halfs = 128 rows x 32 k (64B rows,
// 16B chunks XOR-swizzled by (row&3)).  Consecutive slabs are contiguous.
// ---------------------------------------------------------------------------
__device__ __align__(128) __half g_w1[2][EE * DD * HH];  // [e][ntile(8)][slab(16)][4096]
__device__ __align__(128) __half g_w2[2][EE * HH * DD];  // [e][ntile(4)][slab(32)][4096]
__device__ __align__(128) __half g_apk[BB * 9 * DD];     // [task(9)][btile(8)][slab(16)][4096]
__device__ __align__(128) __half g_hpk[BB * EE * HH];    // [e(18)][btile(8)][slab(32)][4096]
__device__ float g_eo  [BB * EE * DD];
__device__ float g_gate[BB * 9 * EE];
__device__ float g_x1  [BB * 9 * DD];

// ---------------------------------------------------------------------------
__device__ __forceinline__ uint32_t smem_u32(const void* p) {
    uint32_t a;
    asm("{ .reg .u64 t; cvta.to.shared.u64 t, %1; cvt.u32.u64 %0, t; }" : "=r"(a) : "l"(p));
    return a;
}
#define MBARRIER_INIT(addr, cnt) \
    asm volatile("mbarrier.init.shared.b64 [%0], %1;" :: "r"((uint32_t)(addr)), "r"((uint32_t)(cnt)) : "memory")
#define MBARRIER_EXPECT_TX(addr, bytes) \
    asm volatile("mbarrier.arrive.expect_tx.shared.b64 _, [%0], %1;" :: "r"((uint32_t)(addr)), "r"((uint32_t)(bytes)) : "memory")
#define BULK_LOAD(dst, src, bytes, mbar) \
    asm volatile("cp.async.bulk.shared::cluster.global.mbarrier::complete_tx::bytes [%0], [%1], %2, [%3];" \
        :: "r"((uint32_t)(dst)), "l"(src), "r"((uint32_t)(bytes)), "r"((uint32_t)(mbar)) : "memory")
#define MBARRIER_WAIT_PARITY(mbar_smem_addr, phase_parity) do { \
    uint32_t _mbar = (uint32_t)(mbar_smem_addr); \
    uint32_t _parity = (uint32_t)(phase_parity); \
    uint32_t _done; \
    asm volatile("{\n\t.reg .pred p;\n\tmbarrier.try_wait.parity.acquire.cta.shared::cta.b64 p, [%1], %2;\n\tselp.b32 %0, 1, 0, p;\n\t}" \
        : "=r"(_done) : "r"(_mbar), "r"(_parity) : "memory"); \
    if (!_done) { \
        asm volatile("{\n\t.reg .pred P1;\n\tWAIT_LOOP_%=:\n\tmbarrier.try_wait.parity.acquire.cta.shared::cta.b64 P1, [%0], %1, 0x989680;\n\t@P1 bra.uni WAIT_DONE_%=;\n\tbra.uni WAIT_LOOP_%=;\n\tWAIT_DONE_%=:\n\t}" \
            :: "r"(_mbar), "r"(_parity) : "memory"); \
    } \
} while(0)

#define LDSM4(r, addr) \
    asm volatile("ldmatrix.sync.aligned.m8n8.x4.shared.b16 {%0,%1,%2,%3}, [%4];" \
        : "=r"((r)[0]), "=r"((r)[1]), "=r"((r)[2]), "=r"((r)[3]) : "r"(addr))

__device__ __forceinline__ void mma16816(float* c, const uint32_t* a, const uint32_t* b) {
    asm volatile(
        "mma.sync.aligned.m16n8k16.row.col.f32.f16.f16.f32 "
        "{%0,%1,%2,%3}, {%4,%5,%6,%7}, {%8,%9}, {%0,%1,%2,%3};"
        : "+f"(c[0]), "+f"(c[1]), "+f"(c[2]), "+f"(c[3])
        : "r"(a[0]), "r"(a[1]), "r"(a[2]), "r"(a[3]), "r"(b[0]), "r"(b[1]));
}

// Packed offset for element (row 0..127, kk 0..31) within one 4096-half slab.
__device__ __forceinline__ int pk_off(int row, int kk) {
    const int chunk = kk >> 3;
    return row * 32 + (((chunk) ^ (row & 3)) << 3) + (kk & 7);
}

// ===========================================================================
// Conversion kernels (run once per launch)
// ===========================================================================
// inputs (B,9,D) fp32 -> apk [m][b>>7][d>>5][pk(row=b&127, kk=d&31)]
__global__ __launch_bounds__(128) void conv_act(
    const float* __restrict__ src, __half* __restrict__ apk)
{
    const int b = blockIdx.x, m = blockIdx.y, d = threadIdx.x * 4;
    float4 v = *(const float4*)(src + ((size_t)b * 9 + m) * DD + d);
    __half h[4];
    h[0] = __float2half_rn(v.x); h[1] = __float2half_rn(v.y);
    h[2] = __float2half_rn(v.z); h[3] = __float2half_rn(v.w);
    const size_t off = (((size_t)m * 8 + (b >> 7)) * (DD / 32) + (d >> 5)) * 4096
                     + pk_off(b & 127, d & 31);
    *(uint2*)(apk + off) = *(uint2*)h;
}

// W[e][k][n] fp32 -> Wpk [e][n>>7][k>>5][pk(row=n&127, kk=k&31)]
__global__ __launch_bounds__(256) void conv_wt(
    const float* __restrict__ W, __half* __restrict__ Wpk, int Kd, int Nd)
{
    __shared__ float t[32][33];
    const int e  = blockIdx.z;
    const int k0 = blockIdx.x * 32, n0 = blockIdx.y * 32;
    const int r = threadIdx.x >> 3;     // 0..31
    const int c = threadIdx.x & 7;      // 0..7
    const float* We = W + (size_t)e * Kd * Nd;

    float4 v = *(const float4*)(We + (size_t)(k0 + r) * Nd + n0 + c * 4);
    t[r][c * 4 + 0] = v.x; t[r][c * 4 + 1] = v.y;
    t[r][c * 4 + 2] = v.z; t[r][c * 4 + 3] = v.w;
    __syncthreads();

    __half h[4];
    h[0] = __float2half_rn(t[c * 4 + 0][r]);
    h[1] = __float2half_rn(t[c * 4 + 1][r]);
    h[2] = __float2half_rn(t[c * 4 + 2][r]);
    h[3] = __float2half_rn(t[c * 4 + 3][r]);
    const int n = n0 + r;
    const size_t off = (((size_t)e * (Nd / 128) + (n >> 7)) * (Kd / 32) + (k0 >> 5)) * 4096
                     + pk_off(n & 127, c * 4);
    *(uint2*)(Wpk + off) = *(uint2*)h;
}

// ===========================================================================
// Tensor-core expert GEMM, single-product fp16, packed bulk-copy operands:
//   C[b,e,n] = act( sum_k A(b,e)[k] * Bt[e][n][k] + bias[e,n] )
// Tile 128x128, BK=64 per pipeline STAGE (two contiguous packed slabs):
// per stage 2x cp.async.bulk (16KB each) + 1 mbarrier + 1 barrier.
// 3 stages x 32KB = 96KB smem/CTA, 2 CTAs/SM.
// OUT1: relu + write packed h-plane; else fp32 row-major write.
// ===========================================================================
template<bool GATHER, bool OUT1, int NMAT, int K>
__global__ __launch_bounds__(256, 2) void tc_gemm(
    const __half* __restrict__ Apk,
    const __half* __restrict__ Bpk,
    const float* __restrict__ bias,
    float* __restrict__ Cf, __half* __restrict__ Chp)
{
    constexpr int NSTG = K / 64;        // stages: 8 (GEMM1) / 16 (GEMM2)
    constexpr uint32_t PLANE = 16384;   // A (or B) bytes per stage (2 slabs)
    constexpr uint32_t STAGE = 32768;

    extern __shared__ char smraw[];
    __shared__ __align__(8) unsigned long long s_mb[3];
    const uint32_t smbase = smem_u32(smraw);
    const uint32_t mbbase = smem_u32(&s_mb[0]);

    const int e    = blockIdx.z;
    const int n0   = blockIdx.x * 128;
    const int tid  = threadIdx.x;
    const int wid  = tid >> 5;
    const int lane = tid & 31;
    const int g    = lane >> 2;
    const int q    = lane & 3;
    const int mbase = (wid >> 2) * 64;
    const int nbase = (wid & 3) * 32;
    const int xr   = lane & 3;

    const __half* A_b = Apk + ((size_t)(GATHER ? (e >> 1) : e) * 8 + blockIdx.y) * (size_t)(K / 32) * 4096;
    const __half* B_b = Bpk + ((size_t)e * (NMAT / 128) + blockIdx.x) * (size_t)(K / 32) * 4096;

    uint32_t arow[4], brow[2];
    #pragma unroll
    for (int i = 0; i < 4; i++)
        arow[i] = (uint32_t)(mbase + i * 16 + (lane & 15)) * 64u;
    #pragma unroll
    for (int jj = 0; jj < 2; jj++)
        brow[jj] = (uint32_t)(nbase + jj * 16 + (lane & 7) + (((lane >> 4) & 1) << 3)) * 64u;
    const int akc0 = lane >> 4;
    const int bkc0 = (lane >> 3) & 1;

    float acc[4][4][4];
    #pragma unroll
    for (int i = 0; i < 4; i++)
        #pragma unroll
        for (int j = 0; j < 4; j++)
            #pragma unroll
            for (int c = 0; c < 4; c++) acc[i][j][c] = 0.f;

    if (tid == 0) {
        #pragma unroll
        for (int s = 0; s < 3; s++) MBARRIER_INIT(mbbase + s * 8, 1);
    }
    __syncthreads();

    auto issueStage = [&](int t) {
        const int slot = t % 3;
        const uint32_t sb = smbase + (uint32_t)slot * STAGE;
        const uint32_t mb = mbbase + slot * 8;
        MBARRIER_EXPECT_TX(mb, 32768u);
        BULK_LOAD(sb,         A_b + (size_t)t * 8192, 16384u, mb);
        BULK_LOAD(sb + PLANE, B_b + (size_t)t * 8192, 16384u, mb);
    };

    // One 32-K sub-slab: base addresses of its A and B 8KB regions.
    auto computeSub = [&](uint32_t sba, uint32_t sbb) {
        #pragma unroll
        for (int ks = 0; ks < 2; ks++) {
            const uint32_t ao = (uint32_t)(((akc0 + 2 * ks) ^ xr) << 4);
            const uint32_t bo = (uint32_t)(((bkc0 + 2 * ks) ^ xr) << 4);
            uint32_t af[4][4], bf[2][4];
            LDSM4(bf[0], sbb + brow[0] + bo);
            LDSM4(bf[1], sbb + brow[1] + bo);
            #pragma unroll
            for (int i = 0; i < 4; i++)
                LDSM4(af[i], sba + arow[i] + ao);
            #pragma unroll
            for (int i = 0; i < 4; i++)
                #pragma unroll
                for (int j = 0; j < 4; j++)
                    mma16816(acc[i][j], af[i], &bf[j >> 1][(j & 1) * 2]);
        }
    };

    if (tid == 0) { issueStage(0); issueStage(1); }

    for (int t = 0; t < NSTG; t++) {
        const int slot = t % 3;
        MBARRIER_WAIT_PARITY(mbbase + slot * 8, (t / 3) & 1);
        const uint32_t sb = smbase + (uint32_t)slot * STAGE;
        computeSub(sb,        sb + PLANE);
        computeSub(sb + 8192, sb + PLANE + 8192);
        __syncthreads();
        if (tid == 0 && t + 2 < NSTG) issueStage(t + 2);
    }

    // ---- epilogue ----
    if (OUT1) {
        // packed h layout: [e][btile][hslab][pk(row, kk)]
        // This warp's 32 columns live entirely in slab (n0+nbase)>>5.
        const size_t base = (((size_t)e * 8 + blockIdx.y) * (NMAT / 32)
                            + (size_t)((n0 + nbase) >> 5)) * 4096;
        #pragma unroll
        for (int i = 0; i < 4; i++) {
            const int row = mbase + i * 16 + g;      // (row+8)&3 == row&3
            const int sw = (row & 3);
            #pragma unroll
            for (int j = 0; j < 4; j++) {
                const int col = nbase + j * 8 + 2 * q;
                const float2 bb = *(const float2*)(bias + (size_t)e * NMAT + n0 + col);
                float v0 = fmaxf(acc[i][j][0] + bb.x, 0.f);
                float v1 = fmaxf(acc[i][j][1] + bb.y, 0.f);
                float v2 = fmaxf(acc[i][j][2] + bb.x, 0.f);
                float v3 = fmaxf(acc[i][j][3] + bb.y, 0.f);
                __half h[4];
                h[0] = __float2half_rn(v0); h[1] = __float2half_rn(v1);
                h[2] = __float2half_rn(v2); h[3] = __float2half_rn(v3);
                const int inner = ((j ^ sw) << 3) + 2 * q;   // kk = j*8 + 2q within slab
                *(uint32_t*)(Chp + base + (size_t)row * 32 + inner)       = *(uint32_t*)&h[0];
                *(uint32_t*)(Chp + base + (size_t)(row + 8) * 32 + inner) = *(uint32_t*)&h[2];
            }
        }
    } else {
        const int m0 = blockIdx.y * 128;
        #pragma unroll
        for (int i = 0; i < 4; i++) {
            const int rr0 = m0 + mbase + i * 16 + g;
            #pragma unroll
            for (int j = 0; j < 4; j++) {
                const int col = nbase + j * 8 + 2 * q;
                const float2 bb = *(const float2*)(bias + (size_t)e * NMAT + n0 + col);
                const size_t off0 = ((size_t)rr0 * EE + e) * NMAT + n0 + col;
                const size_t off1 = ((size_t)(rr0 + 8) * EE + e) * NMAT + n0 + col;
                *(float2*)(Cf + off0) = make_float2(acc[i][j][0] + bb.x, acc[i][j][1] + bb.y);
                *(float2*)(Cf + off1) = make_float2(acc[i][j][2] + bb.x, acc[i][j][3] + bb.y);
            }
        }
    }
}

// ---------------------------------------------------------------------------
// Gating: g[b,m,:] = softmax( x[b,m,:] @ Wg[m] + bg[m] ) + add(m)
// ---------------------------------------------------------------------------
template<int M>
__global__ __launch_bounds__(256) void gate_kernel(
    const float* __restrict__ x, int xRows,
    const float* __restrict__ Wg, const float* __restrict__ bg,
    const float* __restrict__ sew_task, const float* __restrict__ sew_shared,
    int layer, float* __restrict__ g)
{
    __shared__ float sWg[DD * EE];
    __shared__ float sLog[32][EE];
    const int m  = blockIdx.y;
    const int b0 = blockIdx.x * 32;

    const float* Wgm = Wg + (size_t)m * DD * EE;
    for (int i = threadIdx.x; i < DD * EE; i += 256) sWg[i] = Wgm[i];
    __syncthreads();

    for (int p = threadIdx.x; p < 32 * EE; p += 256) {
        const int bl = p / EE, e = p % EE;
        const float* xr = x + ((size_t)(b0 + bl) * xRows + m) * DD;
        float s = bg[m * EE + e];
        for (int d = 0; d < DD; d += 4) {
            float4 xv = *(const float4*)(xr + d);
            s = fmaf(xv.x, sWg[(d + 0) * EE + e], s);
            s = fmaf(xv.y, sWg[(d + 1) * EE + e], s);
            s = fmaf(xv.z, sWg[(d + 2) * EE + e], s);
            s = fmaf(xv.w, sWg[(d + 3) * EE + e], s);
        }
        sLog[bl][e] = s;
    }
    __syncthreads();

    if (threadIdx.x < 32) {
        const int bl = threadIdx.x;
        float mx = -1e30f;
        #pragma unroll
        for (int e = 0; e < EE; e++) mx = fmaxf(mx, sLog[bl][e]);
        float ex[EE]; float sum = 0.f;
        #pragma unroll
        for (int e = 0; e < EE; e++) { ex[e] = expf(sLog[bl][e] - mx); sum += ex[e]; }
        const float inv = 1.f / sum;
        float* gp = g + ((size_t)(b0 + bl) * M + m) * EE;
        #pragma unroll
        for (int e = 0; e < EE; e++) gp[e] = ex[e] * inv;
        if (m < TT) {
            gp[2 * m + 0] += sew_task[(m * 2 + layer) * 2 + 0];
            gp[2 * m + 1] += sew_task[(m * 2 + layer) * 2 + 1];
        } else {
            gp[16] += sew_shared[0];
            gp[17] += sew_shared[1];
        }
    }
}

// ---------------------------------------------------------------------------
// Combine: out[b,m,d] = sum_e g[b,m,e] * eo[b,e,d]; optionally also write
// the packed fp16 activation plane (feeds next layer's GEMM1).
// ---------------------------------------------------------------------------
template<int M, bool PLANES>
__global__ __launch_bounds__(512) void combine_kernel(
    const float* __restrict__ g, const float* __restrict__ eo,
    float* __restrict__ out, __half* __restrict__ apk)
{
    __shared__ float sg[M * EE];
    const int b = blockIdx.x;
    for (int i = threadIdx.x; i < M * EE; i += 512) sg[i] = g[(size_t)b * M * EE + i];
    __syncthreads();

    const int d = threadIdx.x;
    float acc[M];
    #pragma unroll
    for (int mm = 0; mm < M; mm++) acc[mm] = 0.f;

    const float* eob = eo + (size_t)b * EE * DD + d;
    #pragma unroll
    for (int e = 0; e < EE; e++) {
        const float v = eob[(size_t)e * DD];
        #pragma unroll
        for (int mm = 0; mm < M; mm++) acc[mm] = fmaf(sg[mm * EE + e], v, acc[mm]);
    }
    #pragma unroll
    for (int mm = 0; mm < M; mm++) {
        out[((size_t)b * M + mm) * DD + d] = acc[mm];
        if (PLANES) {
            const size_t off = (((size_t)mm * 8 + (b >> 7)) * (DD / 32) + (d >> 5)) * 4096
                             + pk_off(b & 127, d & 31);
            apk[off] = __float2half_rn(acc[mm]);
        }
    }
}

// ---------------------------------------------------------------------------
extern "C" void kernel_launch(void* const* d_in, const int* in_sizes, int n_in,
                              void* d_out, int out_size)
{
    const float* inputs   = (const float*)d_in[0];
    const float* W1_0     = (const float*)d_in[1];
    const float* b1_0     = (const float*)d_in[2];
    const float* W2_0     = (const float*)d_in[3];
    const float* b2_0     = (const float*)d_in[4];
    const float* Wg_0     = (const float*)d_in[5];
    const float* bg_0     = (const float*)d_in[6];
    const float* W1_1     = (const float*)d_in[7];
    const float* b1_1     = (const float*)d_in[8];
    const float* W2_1     = (const float*)d_in[9];
    const float* b2_1     = (const float*)d_in[10];
    const float* Wg_1     = (const float*)d_in[11];
    const float* bg_1     = (const float*)d_in[12];
    const float* sew_task = (const float*)d_in[13];
    const float* sew_shared = (const float*)d_in[14];

    __half *w1_0p, *w1_1p, *w2_0p, *w2_1p, *apk, *hpk;
    float *p_eo, *p_gate, *p_x1;
    cudaGetSymbolAddress((void**)&w1_0p, g_w1);
    cudaGetSymbolAddress((void**)&w2_0p, g_w2);
    w1_1p = w1_0p + (size_t)EE * DD * HH;
    w2_1p = w2_0p + (size_t)EE * HH * DD;
    cudaGetSymbolAddress((void**)&apk, g_apk);
    cudaGetSymbolAddress((void**)&hpk, g_hpk);
    cudaGetSymbolAddress((void**)&p_eo,   g_eo);
    cudaGetSymbolAddress((void**)&p_gate, g_gate);
    cudaGetSymbolAddress((void**)&p_x1,   g_x1);

    const int SMEM_DYN = 3 * 32768;   // 96 KB (3 stages x 32KB)
    cudaFuncSetAttribute(tc_gemm<true,  true,  HH, DD>,
                         cudaFuncAttributeMaxDynamicSharedMemorySize, SMEM_DYN);
    cudaFuncSetAttribute(tc_gemm<false, false, DD, HH>,
                         cudaFuncAttributeMaxDynamicSharedMemorySize, SMEM_DYN);

    // ---- conversions (once per launch) ----
    conv_wt<<<dim3(DD/32, HH/32, EE), 256>>>(W1_0, w1_0p, DD, HH);
    conv_wt<<<dim3(DD/32, HH/32, EE), 256>>>(W1_1, w1_1p, DD, HH);
    conv_wt<<<dim3(HH/32, DD/32, EE), 256>>>(W2_0, w2_0p, HH, DD);
    conv_wt<<<dim3(HH/32, DD/32, EE), 256>>>(W2_1, w2_1p, HH, DD);
    conv_act<<<dim3(BB, 9), 128>>>(inputs, apk);

    const dim3 blk(256);

    // ---- Layer 0 ----
    tc_gemm<true,  true,  HH, DD><<<dim3(HH/128, BB/128, EE), blk, SMEM_DYN>>>(
        apk, w1_0p, b1_0, nullptr, hpk);
    tc_gemm<false, false, DD, HH><<<dim3(DD/128, BB/128, EE), blk, SMEM_DYN>>>(
        hpk, w2_0p, b2_0, p_eo, nullptr);
    gate_kernel<9><<<dim3(BB/32, 9), blk>>>(inputs, 9, Wg_0, bg_0, sew_task, sew_shared, 0, p_gate);
    combine_kernel<9, true><<<BB, 512>>>(p_gate, p_eo, p_x1, apk);

    // ---- Layer 1 ----
    tc_gemm<true,  true,  HH, DD><<<dim3(HH/128, BB/128, EE), blk, SMEM_DYN>>>(
        apk, w1_1p, b1_1, nullptr, hpk);
    tc_gemm<false, false, DD, HH><<<dim3(DD/128, BB/128, EE), blk, SMEM_DYN>>>(
        hpk, w2_1p, b2_1, p_eo, nullptr);
    gate_kernel<8><<<dim3(BB/32, 8), blk>>>(p_x1, 9, Wg_1, bg_1, sew_task, sew_shared, 1, p_gate);
    combine_kernel<8, false><<<BB, 512>>>(p_gate, p_eo, (float*)d_out, nullptr);
}

// round 17
// speedup vs baseline: 1.7596x; 1.0929x over previous
#include <cuda_runtime.h>
#include <cuda_fp16.h>
#include <cstdint>
#include <math.h>

#define BB 1024
#define DD 512
#define HH 1024
#define TT 8
#define EE 18

// ---------------------------------------------------------------------------
// Device scratch (no cudaMalloc allowed). All packed operand arrays use the
// tiled layout: [...][tile][slab] -> 4096 halfs = 128 rows x 32 k (64B rows,
// 16B chunks XOR-swizzled by (row&3)).  Consecutive slabs are contiguous.
// ---------------------------------------------------------------------------
__device__ __align__(128) __half g_w1[2][EE * DD * HH];  // [e][ntile(8)][slab(16)][4096]
__device__ __align__(128) __half g_w2[2][EE * HH * DD];  // [e][ntile(4)][slab(32)][4096]
__device__ __align__(128) __half g_apk[BB * 9 * DD];     // [task(9)][btile(8)][slab(16)][4096]
__device__ __align__(128) __half g_hpk[BB * EE * HH];    // [e(18)][btile(8)][slab(32)][4096]
__device__ float g_eo  [BB * EE * DD];
__device__ float g_gate[BB * 9 * EE];
__device__ float g_x1  [BB * 9 * DD];

// ---------------------------------------------------------------------------
__device__ __forceinline__ uint32_t smem_u32(const void* p) {
    uint32_t a;
    asm("{ .reg .u64 t; cvta.to.shared.u64 t, %1; cvt.u32.u64 %0, t; }" : "=r"(a) : "l"(p));
    return a;
}
#define MBARRIER_INIT(addr, cnt) \
    asm volatile("mbarrier.init.shared.b64 [%0], %1;" :: "r"((uint32_t)(addr)), "r"((uint32_t)(cnt)) : "memory")
#define MBARRIER_EXPECT_TX(addr, bytes) \
    asm volatile("mbarrier.arrive.expect_tx.shared.b64 _, [%0], %1;" :: "r"((uint32_t)(addr)), "r"((uint32_t)(bytes)) : "memory")
#define BULK_LOAD(dst, src, bytes, mbar) \
    asm volatile("cp.async.bulk.shared::cluster.global.mbarrier::complete_tx::bytes [%0], [%1], %2, [%3];" \
        :: "r"((uint32_t)(dst)), "l"(src), "r"((uint32_t)(bytes)), "r"((uint32_t)(mbar)) : "memory")
#define MBARRIER_WAIT_PARITY(mbar_smem_addr, phase_parity) do { \
    uint32_t _mbar = (uint32_t)(mbar_smem_addr); \
    uint32_t _parity = (uint32_t)(phase_parity); \
    uint32_t _done; \
    asm volatile("{\n\t.reg .pred p;\n\tmbarrier.try_wait.parity.acquire.cta.shared::cta.b64 p, [%1], %2;\n\tselp.b32 %0, 1, 0, p;\n\t}" \
        : "=r"(_done) : "r"(_mbar), "r"(_parity) : "memory"); \
    if (!_done) { \
        asm volatile("{\n\t.reg .pred P1;\n\tWAIT_LOOP_%=:\n\tmbarrier.try_wait.parity.acquire.cta.shared::cta.b64 P1, [%0], %1, 0x989680;\n\t@P1 bra.uni WAIT_DONE_%=;\n\tbra.uni WAIT_LOOP_%=;\n\tWAIT_DONE_%=:\n\t}" \
            :: "r"(_mbar), "r"(_parity) : "memory"); \
    } \
} while(0)

#define LDSM4(r, addr) \
    asm volatile("ldmatrix.sync.aligned.m8n8.x4.shared.b16 {%0,%1,%2,%3}, [%4];" \
        : "=r"((r)[0]), "=r"((r)[1]), "=r"((r)[2]), "=r"((r)[3]) : "r"(addr))

__device__ __forceinline__ void mma16816(float* c, const uint32_t* a, const uint32_t* b) {
    asm volatile(
        "mma.sync.aligned.m16n8k16.row.col.f32.f16.f16.f32 "
        "{%0,%1,%2,%3}, {%4,%5,%6,%7}, {%8,%9}, {%0,%1,%2,%3};"
        : "+f"(c[0]), "+f"(c[1]), "+f"(c[2]), "+f"(c[3])
        : "r"(a[0]), "r"(a[1]), "r"(a[2]), "r"(a[3]), "r"(b[0]), "r"(b[1]));
}

// Packed offset for element (row 0..127, kk 0..31) within one 4096-half slab.
__device__ __forceinline__ int pk_off(int row, int kk) {
    const int chunk = kk >> 3;
    return row * 32 + (((chunk) ^ (row & 3)) << 3) + (kk & 7);
}

// ===========================================================================
// Conversion kernels (run once per launch)
// ===========================================================================
// inputs (B,9,D) fp32 -> apk [m][b>>7][d>>5][pk(row=b&127, kk=d&31)]
__global__ __launch_bounds__(128) void conv_act(
    const float* __restrict__ src, __half* __restrict__ apk)
{
    const int b = blockIdx.x, m = blockIdx.y, d = threadIdx.x * 4;
    float4 v = *(const float4*)(src + ((size_t)b * 9 + m) * DD + d);
    __half h[4];
    h[0] = __float2half_rn(v.x); h[1] = __float2half_rn(v.y);
    h[2] = __float2half_rn(v.z); h[3] = __float2half_rn(v.w);
    const size_t off = (((size_t)m * 8 + (b >> 7)) * (DD / 32) + (d >> 5)) * 4096
                     + pk_off(b & 127, d & 31);
    *(uint2*)(apk + off) = *(uint2*)h;
}

// W[e][k][n] fp32 -> Wpk [e][n>>7][k>>5][pk(row=n&127, kk=k&31)]
__global__ __launch_bounds__(256) void conv_wt(
    const float* __restrict__ W, __half* __restrict__ Wpk, int Kd, int Nd)
{
    __shared__ float t[32][33];
    const int e  = blockIdx.z;
    const int k0 = blockIdx.x * 32, n0 = blockIdx.y * 32;
    const int r = threadIdx.x >> 3;     // 0..31
    const int c = threadIdx.x & 7;      // 0..7
    const float* We = W + (size_t)e * Kd * Nd;

    float4 v = *(const float4*)(We + (size_t)(k0 + r) * Nd + n0 + c * 4);
    t[r][c * 4 + 0] = v.x; t[r][c * 4 + 1] = v.y;
    t[r][c * 4 + 2] = v.z; t[r][c * 4 + 3] = v.w;
    __syncthreads();

    __half h[4];
    h[0] = __float2half_rn(t[c * 4 + 0][r]);
    h[1] = __float2half_rn(t[c * 4 + 1][r]);
    h[2] = __float2half_rn(t[c * 4 + 2][r]);
    h[3] = __float2half_rn(t[c * 4 + 3][r]);
    const int n = n0 + r;
    const size_t off = (((size_t)e * (Nd / 128) + (n >> 7)) * (Kd / 32) + (k0 >> 5)) * 4096
                     + pk_off(n & 127, c * 4);
    *(uint2*)(Wpk + off) = *(uint2*)h;
}

// ===========================================================================
// Tensor-core expert GEMM, single-product fp16, packed bulk-copy operands:
//   C[b,e,n] = act( sum_k A(b,e)[k] * Bt[e][n][k] + bias[e,n] )
// Tile 128x128, BK=64 per pipeline STAGE (two contiguous packed slabs):
// per stage 2x cp.async.bulk (16KB each) + 1 mbarrier + 1 barrier.
// 3 stages x 32KB = 96KB smem/CTA, 2 CTAs/SM.
// OUT1: relu + write packed h-plane; else fp32 row-major write.
// ===========================================================================
template<bool GATHER, bool OUT1, int NMAT, int K>
__global__ __launch_bounds__(256, 2) void tc_gemm(
    const __half* __restrict__ Apk,
    const __half* __restrict__ Bpk,
    const float* __restrict__ bias,
    float* __restrict__ Cf, __half* __restrict__ Chp)
{
    constexpr int NSTG = K / 64;        // stages: 8 (GEMM1) / 16 (GEMM2)
    constexpr uint32_t PLANE = 16384;   // A (or B) bytes per stage (2 slabs)
    constexpr uint32_t STAGE = 32768;

    extern __shared__ char smraw[];
    __shared__ __align__(8) unsigned long long s_mb[3];
    const uint32_t smbase = smem_u32(smraw);
    const uint32_t mbbase = smem_u32(&s_mb[0]);

    const int e    = blockIdx.z;
    const int n0   = blockIdx.x * 128;
    const int tid  = threadIdx.x;
    const int wid  = tid >> 5;
    const int lane = tid & 31;
    const int g    = lane >> 2;
    const int q    = lane & 3;
    const int mbase = (wid >> 2) * 64;
    const int nbase = (wid & 3) * 32;
    const int xr   = lane & 3;

    const __half* A_b = Apk + ((size_t)(GATHER ? (e >> 1) : e) * 8 + blockIdx.y) * (size_t)(K / 32) * 4096;
    const __half* B_b = Bpk + ((size_t)e * (NMAT / 128) + blockIdx.x) * (size_t)(K / 32) * 4096;

    uint32_t arow[4], brow[2];
    #pragma unroll
    for (int i = 0; i < 4; i++)
        arow[i] = (uint32_t)(mbase + i * 16 + (lane & 15)) * 64u;
    #pragma unroll
    for (int jj = 0; jj < 2; jj++)
        brow[jj] = (uint32_t)(nbase + jj * 16 + (lane & 7) + (((lane >> 4) & 1) << 3)) * 64u;
    const int akc0 = lane >> 4;
    const int bkc0 = (lane >> 3) & 1;

    float acc[4][4][4];
    #pragma unroll
    for (int i = 0; i < 4; i++)
        #pragma unroll
        for (int j = 0; j < 4; j++)
            #pragma unroll
            for (int c = 0; c < 4; c++) acc[i][j][c] = 0.f;

    if (tid == 0) {
        #pragma unroll
        for (int s = 0; s < 3; s++) MBARRIER_INIT(mbbase + s * 8, 1);
    }
    __syncthreads();

    auto issueStage = [&](int t) {
        const int slot = t % 3;
        const uint32_t sb = smbase + (uint32_t)slot * STAGE;
        const uint32_t mb = mbbase + slot * 8;
        MBARRIER_EXPECT_TX(mb, 32768u);
        BULK_LOAD(sb,         A_b + (size_t)t * 8192, 16384u, mb);
        BULK_LOAD(sb + PLANE, B_b + (size_t)t * 8192, 16384u, mb);
    };

    // One 32-K sub-slab: base addresses of its A and B 8KB regions.
    auto computeSub = [&](uint32_t sba, uint32_t sbb) {
        #pragma unroll
        for (int ks = 0; ks < 2; ks++) {
            const uint32_t ao = (uint32_t)(((akc0 + 2 * ks) ^ xr) << 4);
            const uint32_t bo = (uint32_t)(((bkc0 + 2 * ks) ^ xr) << 4);
            uint32_t af[4][4], bf[2][4];
            LDSM4(bf[0], sbb + brow[0] + bo);
            LDSM4(bf[1], sbb + brow[1] + bo);
            #pragma unroll
            for (int i = 0; i < 4; i++)
                LDSM4(af[i], sba + arow[i] + ao);
            #pragma unroll
            for (int i = 0; i < 4; i++)
                #pragma unroll
                for (int j = 0; j < 4; j++)
                    mma16816(acc[i][j], af[i], &bf[j >> 1][(j & 1) * 2]);
        }
    };

    if (tid == 0) { issueStage(0); issueStage(1); }

    for (int t = 0; t < NSTG; t++) {
        const int slot = t % 3;
        MBARRIER_WAIT_PARITY(mbbase + slot * 8, (t / 3) & 1);
        const uint32_t sb = smbase + (uint32_t)slot * STAGE;
        computeSub(sb,        sb + PLANE);
        computeSub(sb + 8192, sb + PLANE + 8192);
        __syncthreads();
        if (tid == 0 && t + 2 < NSTG) issueStage(t + 2);
    }

    // ---- epilogue ----
    if (OUT1) {
        // packed h layout: [e][btile][hslab][pk(row, kk)]
        // This warp's 32 columns live entirely in slab (n0+nbase)>>5.
        const size_t base = (((size_t)e * 8 + blockIdx.y) * (NMAT / 32)
                            + (size_t)((n0 + nbase) >> 5)) * 4096;
        #pragma unroll
        for (int i = 0; i < 4; i++) {
            const int row = mbase + i * 16 + g;      // (row+8)&3 == row&3
            const int sw = (row & 3);
            #pragma unroll
            for (int j = 0; j < 4; j++) {
                const int col = nbase + j * 8 + 2 * q;
                const float2 bb = *(const float2*)(bias + (size_t)e * NMAT + n0 + col);
                float v0 = fmaxf(acc[i][j][0] + bb.x, 0.f);
                float v1 = fmaxf(acc[i][j][1] + bb.y, 0.f);
                float v2 = fmaxf(acc[i][j][2] + bb.x, 0.f);
                float v3 = fmaxf(acc[i][j][3] + bb.y, 0.f);
                __half h[4];
                h[0] = __float2half_rn(v0); h[1] = __float2half_rn(v1);
                h[2] = __float2half_rn(v2); h[3] = __float2half_rn(v3);
                const int inner = ((j ^ sw) << 3) + 2 * q;   // kk = j*8 + 2q within slab
                *(uint32_t*)(Chp + base + (size_t)row * 32 + inner)       = *(uint32_t*)&h[0];
                *(uint32_t*)(Chp + base + (size_t)(row + 8) * 32 + inner) = *(uint32_t*)&h[2];
            }
        }
    } else {
        const int m0 = blockIdx.y * 128;
        #pragma unroll
        for (int i = 0; i < 4; i++) {
            const int rr0 = m0 + mbase + i * 16 + g;
            #pragma unroll
            for (int j = 0; j < 4; j++) {
                const int col = nbase + j * 8 + 2 * q;
                const float2 bb = *(const float2*)(bias + (size_t)e * NMAT + n0 + col);
                const size_t off0 = ((size_t)rr0 * EE + e) * NMAT + n0 + col;
                const size_t off1 = ((size_t)(rr0 + 8) * EE + e) * NMAT + n0 + col;
                *(float2*)(Cf + off0) = make_float2(acc[i][j][0] + bb.x, acc[i][j][1] + bb.y);
                *(float2*)(Cf + off1) = make_float2(acc[i][j][2] + bb.x, acc[i][j][3] + bb.y);
            }
        }
    }
}

// ---------------------------------------------------------------------------
// Gating: g[b,m,:] = softmax( x[b,m,:] @ Wg[m] + bg[m] ) + add(m)
// ---------------------------------------------------------------------------
template<int M>
__global__ __launch_bounds__(256) void gate_kernel(
    const float* __restrict__ x, int xRows,
    const float* __restrict__ Wg, const float* __restrict__ bg,
    const float* __restrict__ sew_task, const float* __restrict__ sew_shared,
    int layer, float* __restrict__ g)
{
    __shared__ float sWg[DD * EE];
    __shared__ float sLog[32][EE];
    const int m  = blockIdx.y;
    const int b0 = blockIdx.x * 32;

    const float* Wgm = Wg + (size_t)m * DD * EE;
    for (int i = threadIdx.x; i < DD * EE; i += 256) sWg[i] = Wgm[i];
    __syncthreads();

    for (int p = threadIdx.x; p < 32 * EE; p += 256) {
        const int bl = p / EE, e = p % EE;
        const float* xr = x + ((size_t)(b0 + bl) * xRows + m) * DD;
        float s = bg[m * EE + e];
        for (int d = 0; d < DD; d += 4) {
            float4 xv = *(const float4*)(xr + d);
            s = fmaf(xv.x, sWg[(d + 0) * EE + e], s);
            s = fmaf(xv.y, sWg[(d + 1) * EE + e], s);
            s = fmaf(xv.z, sWg[(d + 2) * EE + e], s);
            s = fmaf(xv.w, sWg[(d + 3) * EE + e], s);
        }
        sLog[bl][e] = s;
    }
    __syncthreads();

    if (threadIdx.x < 32) {
        const int bl = threadIdx.x;
        float mx = -1e30f;
        #pragma unroll
        for (int e = 0; e < EE; e++) mx = fmaxf(mx, sLog[bl][e]);
        float ex[EE]; float sum = 0.f;
        #pragma unroll
        for (int e = 0; e < EE; e++) { ex[e] = expf(sLog[bl][e] - mx); sum += ex[e]; }
        const float inv = 1.f / sum;
        float* gp = g + ((size_t)(b0 + bl) * M + m) * EE;
        #pragma unroll
        for (int e = 0; e < EE; e++) gp[e] = ex[e] * inv;
        if (m < TT) {
            gp[2 * m + 0] += sew_task[(m * 2 + layer) * 2 + 0];
            gp[2 * m + 1] += sew_task[(m * 2 + layer) * 2 + 1];
        } else {
            gp[16] += sew_shared[0];
            gp[17] += sew_shared[1];
        }
    }
}

// ---------------------------------------------------------------------------
// Combine: out[b,m,d] = sum_e g[b,m,e] * eo[b,e,d]; optionally also write
// the packed fp16 activation plane (feeds next layer's GEMM1).
// ---------------------------------------------------------------------------
template<int M, bool PLANES>
__global__ __launch_bounds__(512) void combine_kernel(
    const float* __restrict__ g, const float* __restrict__ eo,
    float* __restrict__ out, __half* __restrict__ apk)
{
    __shared__ float sg[M * EE];
    const int b = blockIdx.x;
    for (int i = threadIdx.x; i < M * EE; i += 512) sg[i] = g[(size_t)b * M * EE + i];
    __syncthreads();

    const int d = threadIdx.x;
    float acc[M];
    #pragma unroll
    for (int mm = 0; mm < M; mm++) acc[mm] = 0.f;

    const float* eob = eo + (size_t)b * EE * DD + d;
    #pragma unroll
    for (int e = 0; e < EE; e++) {
        const float v = eob[(size_t)e * DD];
        #pragma unroll
        for (int mm = 0; mm < M; mm++) acc[mm] = fmaf(sg[mm * EE + e], v, acc[mm]);
    }
    #pragma unroll
    for (int mm = 0; mm < M; mm++) {
        out[((size_t)b * M + mm) * DD + d] = acc[mm];
        if (PLANES) {
            const size_t off = (((size_t)mm * 8 + (b >> 7)) * (DD / 32) + (d >> 5)) * 4096
                             + pk_off(b & 127, d & 31);
            apk[off] = __float2half_rn(acc[mm]);
        }
    }
}

// ---------------------------------------------------------------------------
extern "C" void kernel_launch(void* const* d_in, const int* in_sizes, int n_in,
                              void* d_out, int out_size)
{
    const float* inputs   = (const float*)d_in[0];
    const float* W1_0     = (const float*)d_in[1];
    const float* b1_0     = (const float*)d_in[2];
    const float* W2_0     = (const float*)d_in[3];
    const float* b2_0     = (const float*)d_in[4];
    const float* Wg_0     = (const float*)d_in[5];
    const float* bg_0     = (const float*)d_in[6];
    const float* W1_1     = (const float*)d_in[7];
    const float* b1_1     = (const float*)d_in[8];
    const float* W2_1     = (const float*)d_in[9];
    const float* b2_1     = (const float*)d_in[10];
    const float* Wg_1     = (const float*)d_in[11];
    const float* bg_1     = (const float*)d_in[12];
    const float* sew_task = (const float*)d_in[13];
    const float* sew_shared = (const float*)d_in[14];

    __half *w1_0p, *w1_1p, *w2_0p, *w2_1p, *apk, *hpk;
    float *p_eo, *p_gate, *p_x1;
    cudaGetSymbolAddress((void**)&w1_0p, g_w1);
    cudaGetSymbolAddress((void**)&w2_0p, g_w2);
    w1_1p = w1_0p + (size_t)EE * DD * HH;
    w2_1p = w2_0p + (size_t)EE * HH * DD;
    cudaGetSymbolAddress((void**)&apk, g_apk);
    cudaGetSymbolAddress((void**)&hpk, g_hpk);
    cudaGetSymbolAddress((void**)&p_eo,   g_eo);
    cudaGetSymbolAddress((void**)&p_gate, g_gate);
    cudaGetSymbolAddress((void**)&p_x1,   g_x1);

    const int SMEM_DYN = 3 * 32768;   // 96 KB (3 stages x 32KB)
    cudaFuncSetAttribute(tc_gemm<true,  true,  HH, DD>,
                         cudaFuncAttributeMaxDynamicSharedMemorySize, SMEM_DYN);
    cudaFuncSetAttribute(tc_gemm<false, false, DD, HH>,
                         cudaFuncAttributeMaxDynamicSharedMemorySize, SMEM_DYN);

    // ---- side streams + fork/join events (host objects, created once) ----
    static cudaStream_t s1 = nullptr, s2 = nullptr;
    static cudaEvent_t eFork = nullptr, eW20 = nullptr, eW11 = nullptr,
                       eW21 = nullptr, eG0 = nullptr, eC0 = nullptr, eG1 = nullptr;
    if (!s1) {
        cudaStreamCreateWithFlags(&s1, cudaStreamNonBlocking);
        cudaStreamCreateWithFlags(&s2, cudaStreamNonBlocking);
        cudaEventCreateWithFlags(&eFork, cudaEventDisableTiming);
        cudaEventCreateWithFlags(&eW20,  cudaEventDisableTiming);
        cudaEventCreateWithFlags(&eW11,  cudaEventDisableTiming);
        cudaEventCreateWithFlags(&eW21,  cudaEventDisableTiming);
        cudaEventCreateWithFlags(&eG0,   cudaEventDisableTiming);
        cudaEventCreateWithFlags(&eC0,   cudaEventDisableTiming);
        cudaEventCreateWithFlags(&eG1,   cudaEventDisableTiming);
    }

    const dim3 blk(256);

    // ---- fork ----
    cudaEventRecord(eFork, 0);
    cudaStreamWaitEvent(s1, eFork, 0);
    cudaStreamWaitEvent(s2, eFork, 0);

    // side1: remaining weight conversions (overlap with GEMM chain)
    conv_wt<<<dim3(HH/32, DD/32, EE), blk, 0, s1>>>(W2_0, w2_0p, HH, DD);
    cudaEventRecord(eW20, s1);
    conv_wt<<<dim3(DD/32, HH/32, EE), blk, 0, s1>>>(W1_1, w1_1p, DD, HH);
    cudaEventRecord(eW11, s1);
    conv_wt<<<dim3(HH/32, DD/32, EE), blk, 0, s1>>>(W2_1, w2_1p, HH, DD);
    cudaEventRecord(eW21, s1);

    // side2: layer-0 gate (independent of GEMMs)
    gate_kernel<9><<<dim3(BB/32, 9), blk, 0, s2>>>(inputs, 9, Wg_0, bg_0, sew_task, sew_shared, 0, p_gate);
    cudaEventRecord(eG0, s2);

    // main critical path
    conv_wt<<<dim3(DD/32, HH/32, EE), blk>>>(W1_0, w1_0p, DD, HH);
    conv_act<<<dim3(BB, 9), 128>>>(inputs, apk);

    tc_gemm<true,  true,  HH, DD><<<dim3(HH/128, BB/128, EE), blk, SMEM_DYN>>>(
        apk, w1_0p, b1_0, nullptr, hpk);
    cudaStreamWaitEvent(0, eW20, 0);
    tc_gemm<false, false, DD, HH><<<dim3(DD/128, BB/128, EE), blk, SMEM_DYN>>>(
        hpk, w2_0p, b2_0, p_eo, nullptr);
    cudaStreamWaitEvent(0, eG0, 0);
    combine_kernel<9, true><<<BB, 512>>>(p_gate, p_eo, p_x1, apk);
    cudaEventRecord(eC0, 0);

    // side2: layer-1 gate (needs x1 from combine_0), overlaps GEMM1_1
    cudaStreamWaitEvent(s2, eC0, 0);
    gate_kernel<8><<<dim3(BB/32, 8), blk, 0, s2>>>(p_x1, 9, Wg_1, bg_1, sew_task, sew_shared, 1, p_gate);
    cudaEventRecord(eG1, s2);

    cudaStreamWaitEvent(0, eW11, 0);
    tc_gemm<true,  true,  HH, DD><<<dim3(HH/128, BB/128, EE), blk, SMEM_DYN>>>(
        apk, w1_1p, b1_1, nullptr, hpk);
    cudaStreamWaitEvent(0, eW21, 0);
    tc_gemm<false, false, DD, HH><<<dim3(DD/128, BB/128, EE), blk, SMEM_DYN>>>(
        hpk, w2_1p, b2_1, p_eo, nullptr);
    cudaStreamWaitEvent(0, eG1, 0);
    combine_kernel<8, false><<<BB, 512>>>(p_gate, p_eo, (float*)d_out, nullptr);
}